// round 1
// baseline (speedup 1.0000x reference)
#include <cuda_runtime.h>

#define CHANNELS 512
#define BATCH    32
#define HW       4096
#define POS      7

// Scratch for per-(b,c) means. __device__ global: allocation-free.
__device__ float g_pooled[BATCH * CHANNELS];

// ---------------------------------------------------------------------------
// Kernel A: global average pool of x over H*W.
// One block per (b,c) row of 4096 floats. 256 threads * 4 float4 each.
// ---------------------------------------------------------------------------
__global__ void __launch_bounds__(256) pool_kernel(const float* __restrict__ x) {
    const int row = blockIdx.x;  // 0 .. BATCH*CHANNELS-1
    const float4* __restrict__ xr =
        reinterpret_cast<const float4*>(x + (size_t)row * HW);
    const int t = threadIdx.x;

    float s = 0.0f;
#pragma unroll
    for (int k = 0; k < 4; k++) {
        float4 v = xr[t + k * 256];
        s += (v.x + v.y) + (v.z + v.w);
    }
    // warp reduce
#pragma unroll
    for (int o = 16; o; o >>= 1) s += __shfl_xor_sync(0xffffffffu, s, o);

    __shared__ float ws[8];
    if ((t & 31) == 0) ws[t >> 5] = s;
    __syncthreads();
    if (t == 0) {
        float tot = 0.0f;
#pragma unroll
        for (int i = 0; i < 8; i++) tot += ws[i];
        g_pooled[row] = tot * (1.0f / HW);
    }
}

// ---------------------------------------------------------------------------
// Kernel B: per-channel pos-embed mean (separable bilinear weights) +
//           32x512x512 matmul + bias + BN(eval) + ReLU.
// grid = BATCH blocks, 512 threads (one output channel per thread).
// ---------------------------------------------------------------------------
__global__ void __launch_bounds__(CHANNELS) head_kernel(
    const float* __restrict__ pos,     // (512,7,7)
    const float* __restrict__ conv_w,  // (512,512) [o,c]
    const float* __restrict__ conv_b,  // (512)
    const float* __restrict__ gamma,
    const float* __restrict__ beta,
    const float* __restrict__ mean,
    const float* __restrict__ var,
    float* __restrict__ out)           // (32,512)
{
    __shared__ float wx[POS];       // 1-D bilinear source weights (sum = 64)
    __shared__ float ps[CHANNELS];  // pooled[b,c] + P[c]

    const int t = threadIdx.x;
    const int b = blockIdx.x;

    if (t < POS) wx[t] = 0.0f;
    __syncthreads();

    // Half-pixel bilinear mapping 64 -> 7. Edge handling: clamping src to
    // [0,6] reproduces both torch align_corners=False and jax's normalized
    // triangle weights (identical for upsampling).
    if (t < 64) {
        float src = (t + 0.5f) * (7.0f / 64.0f) - 0.5f;
        src = fminf(fmaxf(src, 0.0f), 6.0f);
        int j0 = (int)floorf(src);
        if (j0 > 5) j0 = 5;
        float f = src - (float)j0;
        atomicAdd(&wx[j0], 1.0f - f);
        atomicAdd(&wx[j0 + 1], f);
    }
    __syncthreads();

    // P[c] = mean over 64x64 of bilinear-upsampled pos_embed channel c
    //      = (wx ⊗ wx) · pos[c] / 4096     (separable; H == W)
    {
        float P = 0.0f;
        const float* __restrict__ pc = pos + t * (POS * POS);
#pragma unroll
        for (int a = 0; a < POS; a++) {
            float r = 0.0f;
#pragma unroll
            for (int j = 0; j < POS; j++) r += wx[j] * pc[a * POS + j];
            P += wx[a] * r;
        }
        ps[t] = g_pooled[b * CHANNELS + t] + P * (1.0f / HW);
    }
    __syncthreads();

    // y[b,t] = sum_c ps[c] * conv_w[t,c]
    const float4* __restrict__ wrow =
        reinterpret_cast<const float4*>(conv_w + (size_t)t * CHANNELS);
    float acc = 0.0f;
#pragma unroll 8
    for (int c4 = 0; c4 < CHANNELS / 4; c4++) {
        float4 w = wrow[c4];
        acc += w.x * ps[c4 * 4 + 0] + w.y * ps[c4 * 4 + 1] +
               w.z * ps[c4 * 4 + 2] + w.w * ps[c4 * 4 + 3];
    }

    float y = acc + conv_b[t];
    y = gamma[t] * (y - mean[t]) * rsqrtf(var[t] + 1e-5f) + beta[t];
    out[b * CHANNELS + t] = fmaxf(y, 0.0f);
}

// ---------------------------------------------------------------------------
extern "C" void kernel_launch(void* const* d_in, const int* in_sizes, int n_in,
                              void* d_out, int out_size) {
    const float* x      = (const float*)d_in[0];
    const float* pos    = (const float*)d_in[1];
    const float* conv_w = (const float*)d_in[2];
    const float* conv_b = (const float*)d_in[3];
    const float* gamma  = (const float*)d_in[4];
    const float* beta   = (const float*)d_in[5];
    const float* mean   = (const float*)d_in[6];
    const float* var    = (const float*)d_in[7];
    float* out = (float*)d_out;

    pool_kernel<<<BATCH * CHANNELS, 256>>>(x);
    head_kernel<<<BATCH, CHANNELS>>>(pos, conv_w, conv_b,
                                     gamma, beta, mean, var, out);
}

// round 2
// speedup vs baseline: 1.7789x; 1.7789x over previous
#include <cuda_runtime.h>

#define CHANNELS 512
#define BATCH    32
#define HW       4096
#define POS      7

#define OT 8          // output channels per head block
#define BT 8          // batches per head block
#define STR 513       // smem stride (conflict-free)

__device__ float g_pooled[BATCH * CHANNELS];
__device__ float g_P[CHANNELS];   // per-channel pos-embed mean contribution

// ---------------------------------------------------------------------------
// Kernel A: global average pool of x over H*W (blocks 0..16383),
//           plus pos-embed channel means (blocks 16384..16385).
// ---------------------------------------------------------------------------
__global__ void __launch_bounds__(256) pool_kernel(const float* __restrict__ x,
                                                   const float* __restrict__ pos) {
    const int t = threadIdx.x;

    if (blockIdx.x < BATCH * CHANNELS) {
        const int row = blockIdx.x;
        const float4* __restrict__ xr =
            reinterpret_cast<const float4*>(x + (size_t)row * HW);
        float s = 0.0f;
#pragma unroll
        for (int k = 0; k < 4; k++) {
            float4 v = xr[t + k * 256];
            s += (v.x + v.y) + (v.z + v.w);
        }
#pragma unroll
        for (int o = 16; o; o >>= 1) s += __shfl_xor_sync(0xffffffffu, s, o);

        __shared__ float ws[8];
        if ((t & 31) == 0) ws[t >> 5] = s;
        __syncthreads();
        if (t == 0) {
            float tot = 0.0f;
#pragma unroll
            for (int i = 0; i < 8; i++) tot += ws[i];
            g_pooled[row] = tot * (1.0f / HW);
        }
    } else {
        // pos-embed mean blocks: 2 blocks x 256 threads = 512 channels
        __shared__ float wx[POS];
        if (t < POS) wx[t] = 0.0f;
        __syncthreads();
        // Half-pixel bilinear 64->7 source weights (clamped; sum over 64 = 64).
        if (t < 64) {
            float src = (t + 0.5f) * (7.0f / 64.0f) - 0.5f;
            src = fminf(fmaxf(src, 0.0f), 6.0f);
            int j0 = (int)floorf(src);
            if (j0 > 5) j0 = 5;
            float f = src - (float)j0;
            atomicAdd(&wx[j0], 1.0f - f);
            atomicAdd(&wx[j0 + 1], f);
        }
        __syncthreads();

        const int c = (blockIdx.x - BATCH * CHANNELS) * 256 + t;
        const float* __restrict__ pc = pos + c * (POS * POS);
        float P = 0.0f;
#pragma unroll
        for (int a = 0; a < POS; a++) {
            float r = 0.0f;
#pragma unroll
            for (int j = 0; j < POS; j++) r += wx[j] * pc[a * POS + j];
            P += wx[a] * r;
        }
        g_P[c] = P * (1.0f / HW);
    }
}

// ---------------------------------------------------------------------------
// Kernel B: tiled 32x512x512 matmul + bias + BN(eval) + ReLU.
// grid = (512/OT, 32/BT) = (64, 4), 256 threads.
// Thread t: o_l = t&7, b_l = (t>>3)&7, part = t>>6 (4 c-parts of 128).
// ---------------------------------------------------------------------------
__global__ void __launch_bounds__(256) head_kernel(
    const float* __restrict__ conv_w,  // (512,512) [o,c]
    const float* __restrict__ conv_b,
    const float* __restrict__ gamma,
    const float* __restrict__ beta,
    const float* __restrict__ mean,
    const float* __restrict__ var,
    float* __restrict__ out)           // (32,512)
{
    __shared__ float Wt[OT * STR];
    __shared__ float Pt[BT * STR];
    __shared__ float red[OT * BT * 4];

    const int t  = threadIdx.x;
    const int o0 = blockIdx.x * OT;
    const int b0 = blockIdx.y * BT;

    // Stage W tile: 8 rows x 512 floats = 1024 float4, 4 per thread.
    {
        const float4* __restrict__ wsrc =
            reinterpret_cast<const float4*>(conv_w + (size_t)o0 * CHANNELS);
#pragma unroll
        for (int k = 0; k < 4; k++) {
            int i = t + k * 256;            // float4 index within tile
            float4 v = wsrc[i];
            int row = i >> 7;               // /128 float4 per row
            int col = (i & 127) << 2;
            float* d = &Wt[row * STR + col];
            d[0] = v.x; d[1] = v.y; d[2] = v.z; d[3] = v.w;
        }
    }
    // Stage P tile: pooled + g_P, 8 rows x 512.
    {
#pragma unroll
        for (int k = 0; k < 4; k++) {
            int i = t + k * 256;
            int row = i >> 7;
            int col = (i & 127) << 2;
            const float4 v = *reinterpret_cast<const float4*>(
                &g_pooled[(b0 + row) * CHANNELS + col]);
            const float4 p = *reinterpret_cast<const float4*>(&g_P[col]);
            float* d = &Pt[row * STR + col];
            d[0] = v.x + p.x; d[1] = v.y + p.y; d[2] = v.z + p.z; d[3] = v.w + p.w;
        }
    }
    __syncthreads();

    const int o_l  = t & 7;
    const int b_l  = (t >> 3) & 7;
    const int part = t >> 6;

    const float* __restrict__ wr = &Wt[o_l * STR + part * 128];
    const float* __restrict__ pr = &Pt[b_l * STR + part * 128];
    float acc = 0.0f;
#pragma unroll 16
    for (int c = 0; c < 128; c++) acc += wr[c] * pr[c];

    red[(o_l * BT + b_l) * 4 + part] = acc;
    __syncthreads();

    if (t < OT * BT) {
        const int ol = t & 7;
        const int bl = t >> 3;
        const float* r = &red[(ol * BT + bl) * 4];
        float y = (r[0] + r[1]) + (r[2] + r[3]);
        const int o = o0 + ol;
        y += conv_b[o];
        y = gamma[o] * (y - mean[o]) * rsqrtf(var[o] + 1e-5f) + beta[o];
        out[(b0 + bl) * CHANNELS + o] = fmaxf(y, 0.0f);
    }
}

// ---------------------------------------------------------------------------
extern "C" void kernel_launch(void* const* d_in, const int* in_sizes, int n_in,
                              void* d_out, int out_size) {
    const float* x      = (const float*)d_in[0];
    const float* pos    = (const float*)d_in[1];
    const float* conv_w = (const float*)d_in[2];
    const float* conv_b = (const float*)d_in[3];
    const float* gamma  = (const float*)d_in[4];
    const float* beta   = (const float*)d_in[5];
    const float* mean   = (const float*)d_in[6];
    const float* var    = (const float*)d_in[7];
    float* out = (float*)d_out;

    pool_kernel<<<BATCH * CHANNELS + 2, 256>>>(x, pos);
    head_kernel<<<dim3(CHANNELS / OT, BATCH / BT), 256>>>(
        conv_w, conv_b, gamma, beta, mean, var, out);
}